// round 9
// baseline (speedup 1.0000x reference)
#include <cuda_runtime.h>
#include <cstdint>

// out[n] = w_mp * sum_{e : dst[e]==n} ew[e] * x[src[e]]
// x: [N,32] f32, edge_index: [2,E] int32, ew: [E] f32, w_mp: [1] f32
//
// Two-launch pipeline: bucket-permute -> per-node register gather.
// Gather v2: records prefetched to registers (shfl-broadcast), lane=column,
// 4 independent x-row loads in flight per step (kills the latency chain).

#define N_MAX 120000
#define CAP   64          // Poisson(16): P(deg>=64) ~ 1e-19 per node
#define SPILL_MAX 4096

__device__ int g_cnt[N_MAX];                               // zero-init
__device__ unsigned long long g_rec[(size_t)N_MAX * CAP];  // (bits(ew)<<32)|src
__device__ int g_spill_cnt;                                // zero-init
__device__ int g_spill_dst[SPILL_MAX];
__device__ unsigned long long g_spill_rec[SPILL_MAX];

// ---------- K1: one-pass bucket permute (2 edges/thread) ----------
__device__ __forceinline__ void permute_one(int s, int d, float w) {
    int pos = atomicAdd(&g_cnt[d], 1);
    unsigned long long r =
        ((unsigned long long)__float_as_uint(w) << 32) | (unsigned)s;
    if (pos < CAP) {
        g_rec[(size_t)d * CAP + pos] = r;
    } else {
        int sp = atomicAdd(&g_spill_cnt, 1);
        if (sp < SPILL_MAX) { g_spill_dst[sp] = d; g_spill_rec[sp] = r; }
    }
}

__global__ __launch_bounds__(256)
void k_permute(const int* __restrict__ ei, const float* __restrict__ ew, int E) {
    int t = blockIdx.x * blockDim.x + threadIdx.x;
    int e = t * 2;
    if (e + 1 < E) {
        int2   s2 = __ldg(reinterpret_cast<const int2*>(ei + e));
        int2   d2 = __ldg(reinterpret_cast<const int2*>(ei + E + e));
        float2 w2 = __ldg(reinterpret_cast<const float2*>(ew + e));
        permute_one(s2.x, d2.x, w2.x);
        permute_one(s2.y, d2.y, w2.y);
    } else if (e < E) {
        permute_one(__ldg(&ei[e]), __ldg(&ei[E + e]), __ldg(&ew[e]));
    }
}

// ---------- K2: per-node gather, warp per node; resets counters ----------
__global__ __launch_bounds__(256)
void k_gather(const float* __restrict__ x, const float* __restrict__ w_mp,
              float* __restrict__ out, int n) {
    const unsigned FULL = 0xffffffffu;
    int node = (blockIdx.x * blockDim.x + threadIdx.x) >> 5;
    if (node >= n) return;
    int lane = threadIdx.x & 31;    // lane = feature column

    int raw_cnt = __ldg(&g_cnt[node]);
    int cnt = raw_cnt > CAP ? CAP : raw_cnt;
    const unsigned long long* rec = g_rec + (size_t)node * CAP;

    float acc = 0.f;
    for (int base = 0; base < cnt; base += 32) {
        int m = cnt - base; if (m > 32) m = 32;
        // Prefetch up to 32 records, one per lane (coalesced burst).
        unsigned long long r = (lane < m) ? __ldg(&rec[base + lane]) : 0ull;
        unsigned rlo = (unsigned)r;
        unsigned rhi = (unsigned)(r >> 32);

        int k = 0;
        // 4 edges per step: independent row loads issued before any FFMA.
        for (; k + 4 <= m; k += 4) {
            int   s0 = (int)__shfl_sync(FULL, rlo, k + 0);
            int   s1 = (int)__shfl_sync(FULL, rlo, k + 1);
            int   s2 = (int)__shfl_sync(FULL, rlo, k + 2);
            int   s3 = (int)__shfl_sync(FULL, rlo, k + 3);
            float w0 = __uint_as_float(__shfl_sync(FULL, rhi, k + 0));
            float w1 = __uint_as_float(__shfl_sync(FULL, rhi, k + 1));
            float w2 = __uint_as_float(__shfl_sync(FULL, rhi, k + 2));
            float w3 = __uint_as_float(__shfl_sync(FULL, rhi, k + 3));
            float v0 = __ldg(x + (size_t)s0 * 32 + lane);
            float v1 = __ldg(x + (size_t)s1 * 32 + lane);
            float v2 = __ldg(x + (size_t)s2 * 32 + lane);
            float v3 = __ldg(x + (size_t)s3 * 32 + lane);
            acc = fmaf(w0, v0, acc);
            acc = fmaf(w1, v1, acc);
            acc = fmaf(w2, v2, acc);
            acc = fmaf(w3, v3, acc);
        }
        for (; k < m; k++) {
            int   s0 = (int)__shfl_sync(FULL, rlo, k);
            float w0 = __uint_as_float(__shfl_sync(FULL, rhi, k));
            acc = fmaf(w0, __ldg(x + (size_t)s0 * 32 + lane), acc);
        }
    }

    // Spill path (cold; practically never taken).
    if (raw_cnt > CAP) {
        int spills = g_spill_cnt; if (spills > SPILL_MAX) spills = SPILL_MAX;
        for (int i = 0; i < spills; i++) {
            if (g_spill_dst[i] == node) {
                unsigned long long r = g_spill_rec[i];
                float w  = __uint_as_float((unsigned)(r >> 32));
                int  src = (int)(unsigned)r;
                acc = fmaf(w, __ldg(x + (size_t)src * 32 + lane), acc);
            }
        }
    }

    out[(size_t)node * 32 + lane] = acc * __ldg(w_mp);

    // Restore zero-state invariant for the next graph replay.
    if (lane == 0) g_cnt[node] = 0;
    if (node == 0 && lane == 1) g_spill_cnt = 0;
}

// ---------- Fallback (proven round-4 path) ----------
__global__ void k_zero_out(float4* __restrict__ out, int n4) {
    int i = blockIdx.x * blockDim.x + threadIdx.x;
    if (i < n4) out[i] = make_float4(0.f, 0.f, 0.f, 0.f);
}

__global__ __launch_bounds__(256)
void k_scatter_atomic(const float* __restrict__ x, const int* __restrict__ ei,
                      const float* __restrict__ ew, const float* __restrict__ w_mp,
                      float* __restrict__ out, int E) {
    int tid = blockIdx.x * blockDim.x + threadIdx.x;
    int e = tid >> 3, c = tid & 7;
    if (e >= E) return;
    int s = __ldg(&ei[e]);
    int d = __ldg(&ei[E + e]);
    float w = __ldg(&ew[e]) * __ldg(w_mp);
    float4 v = __ldg(reinterpret_cast<const float4*>(x + (size_t)s * 32) + c);
    v.x *= w; v.y *= w; v.z *= w; v.w *= w;
    float* dst = out + (size_t)d * 32 + c * 4;
    asm volatile("red.global.add.v4.f32 [%0], {%1, %2, %3, %4};"
                 :: "l"(dst), "f"(v.x), "f"(v.y), "f"(v.z), "f"(v.w)
                 : "memory");
}

extern "C" void kernel_launch(void* const* d_in, const int* in_sizes, int n_in,
                              void* d_out, int out_size) {
    const float* x    = (const float*)d_in[0];
    const int*   ei   = (const int*)d_in[1];
    const float* ew   = (const float*)d_in[2];
    const float* w_mp = (const float*)d_in[3];
    float* out = (float*)d_out;

    int E = in_sizes[2];
    int n = out_size / 32;   // nodes

    if (n <= N_MAX) {
        int pt = (E + 1) / 2;                       // 2 edges per thread
        k_permute<<<(pt + 255) / 256, 256>>>(ei, ew, E);
        k_gather<<<(n * 32 + 255) / 256, 256>>>(x, w_mp, out, n);
    } else {
        int n4 = out_size / 4;
        k_zero_out<<<(n4 + 255) / 256, 256>>>((float4*)out, n4);
        long long threads = (long long)E * 8;
        k_scatter_atomic<<<(int)((threads + 255) / 256), 256>>>(x, ei, ew, w_mp, out, E);
    }
}